// round 3
// baseline (speedup 1.0000x reference)
#include <cuda_runtime.h>
#include <cstdint>

// SheafConvLayer:
//   out[n,:] = relu( W_self[n] @ x[n] + b_self[n]
//                    + sum_{e: dst[e]==n} ( W_edge[e] @ x[src[e]] + b_edge[e] ) )
// D_IN = D_OUT = 16.
//
// Inputs (metadata order):
//   0: x           f32 [N,16]
//   1: edge_index  int [2,E]   (dtype int32 OR int64 — detected at runtime)
//   2: weight_edge f32 [E,16,16]
//   3: weight_self f32 [N,16,16]
//   4: bias_edge   f32 [E,16]
//   5: bias_self   f32 [N,16]
// out: f32 [N,16]

#define D 16

// Runtime-detected flag: 1 if edge_index is int64, 0 if int32.
__device__ int g_idx_is64;

__device__ __forceinline__ float dot4(float4 a, float4 b) {
    return a.x * b.x + a.y * b.y + a.z * b.z + a.w * b.w;
}

// Vector reduction to global memory (sm_90+): one 16B REDG instead of 4 scalar atomics.
__device__ __forceinline__ void red_add_v4(float* addr, float a, float b, float c, float d) {
    asm volatile("red.global.add.v4.f32 [%0], {%1, %2, %3, %4};"
                 :: "l"(addr), "f"(a), "f"(b), "f"(c), "f"(d)
                 : "memory");
}

// ---------------------------------------------------------------------------
// Kernel 0: dtype detection. If edge_index is int64 with indices < 2^31,
// every odd 32-bit word (high half, little-endian) of the first 1024 pairs
// is zero. For int32 data those words are random node indices, so the
// probability of a false int64 verdict is ~0.
// Reads only the first 2048 int32 words — in-bounds for either dtype.
// ---------------------------------------------------------------------------
__global__ void detect_kernel(const int* __restrict__ eidx_words)
{
    int all_hi_zero = 1;
    for (int i = 0; i < 1024; i++) {
        if (eidx_words[2 * i + 1] != 0) { all_hi_zero = 0; break; }
    }
    g_idx_is64 = all_hi_zero;
}

// ---------------------------------------------------------------------------
// Kernel 1: self term. One thread handles (node, 4-channel group).
// Writes out directly (initializes the poisoned output buffer).
// ---------------------------------------------------------------------------
__global__ void __launch_bounds__(256)
self_kernel(const float* __restrict__ x,
            const float* __restrict__ w_self,
            const float* __restrict__ b_self,
            float* __restrict__ out,
            int n_nodes)
{
    int t = blockIdx.x * blockDim.x + threadIdx.x;
    int total = n_nodes * 4;
    if (t >= total) return;
    int n = t >> 2;
    int q = t & 3;  // channel group: rows q*4 .. q*4+3

    const float4* xp = reinterpret_cast<const float4*>(x + (size_t)n * D);
    float4 x0 = xp[0], x1 = xp[1], x2 = xp[2], x3 = xp[3];

    const float4* wp = reinterpret_cast<const float4*>(w_self + (size_t)n * D * D + (size_t)q * 64);
    float4 bb = reinterpret_cast<const float4*>(b_self + (size_t)n * D)[q];
    float acc[4] = {bb.x, bb.y, bb.z, bb.w};

    #pragma unroll
    for (int r = 0; r < 4; r++) {
        float4 w0 = wp[r * 4 + 0];
        float4 w1 = wp[r * 4 + 1];
        float4 w2 = wp[r * 4 + 2];
        float4 w3 = wp[r * 4 + 3];
        acc[r] += dot4(w0, x0) + dot4(w1, x1) + dot4(w2, x2) + dot4(w3, x3);
    }

    reinterpret_cast<float4*>(out + (size_t)n * D)[q] =
        make_float4(acc[0], acc[1], acc[2], acc[3]);
}

// ---------------------------------------------------------------------------
// Kernel 2: edge messages. One thread handles (edge, 4-channel group).
// Streams 256B of weight_edge, gathers x[src] (L2-resident), one red.v4.f32.
// Index dtype chosen via the runtime flag; OOB indices are skipped (fail
// loudly via rel_err instead of crashing).
// ---------------------------------------------------------------------------
__global__ void __launch_bounds__(256)
edge_kernel(const float* __restrict__ x,
            const void* __restrict__ edge_index,
            const float* __restrict__ w_edge,
            const float* __restrict__ b_edge,
            float* __restrict__ out,
            int n_edges, int n_nodes)
{
    int t = blockIdx.x * blockDim.x + threadIdx.x;
    int total = n_edges * 4;
    if (t >= total) return;
    int e = t >> 2;
    int q = t & 3;

    long long src, dst;
    if (g_idx_is64) {
        const long long* p = (const long long*)edge_index;
        src = p[e];
        dst = p[(size_t)n_edges + e];
    } else {
        const int* p = (const int*)edge_index;
        src = p[e];
        dst = p[(size_t)n_edges + e];
    }
    // Safety clamp: never dereference garbage.
    if (src < 0 || src >= n_nodes || dst < 0 || dst >= n_nodes) return;

    const float4* xp = reinterpret_cast<const float4*>(x + (size_t)src * D);
    float4 x0 = xp[0], x1 = xp[1], x2 = xp[2], x3 = xp[3];

    const float4* wp = reinterpret_cast<const float4*>(w_edge + (size_t)e * D * D + (size_t)q * 64);
    float4 bb = reinterpret_cast<const float4*>(b_edge + (size_t)e * D)[q];
    float acc[4] = {bb.x, bb.y, bb.z, bb.w};

    #pragma unroll
    for (int r = 0; r < 4; r++) {
        float4 w0 = wp[r * 4 + 0];
        float4 w1 = wp[r * 4 + 1];
        float4 w2 = wp[r * 4 + 2];
        float4 w3 = wp[r * 4 + 3];
        acc[r] += dot4(w0, x0) + dot4(w1, x1) + dot4(w2, x2) + dot4(w3, x3);
    }

    red_add_v4(out + (size_t)dst * D + (size_t)q * 4, acc[0], acc[1], acc[2], acc[3]);
}

// ---------------------------------------------------------------------------
// Kernel 3: ReLU over out.
// ---------------------------------------------------------------------------
__global__ void __launch_bounds__(256)
relu_kernel(float* __restrict__ out, int total)
{
    int t = blockIdx.x * blockDim.x + threadIdx.x;
    int stride = gridDim.x * blockDim.x;
    for (int i = t; i < total; i += stride) {
        float v = out[i];
        out[i] = v > 0.0f ? v : 0.0f;
    }
}

extern "C" void kernel_launch(void* const* d_in, const int* in_sizes, int n_in,
                              void* d_out, int out_size)
{
    const float* x      = (const float*)d_in[0];
    const void*  eidx   = d_in[1];
    const float* w_edge = (const float*)d_in[2];
    const float* w_self = (const float*)d_in[3];
    const float* b_edge = (const float*)d_in[4];
    const float* b_self = (const float*)d_in[5];
    float*       out    = (float*)d_out;

    int n_nodes = in_sizes[0] / D;        // x is [N,16]
    int n_edges = in_sizes[2] / (D * D);  // weight_edge is [E,16,16] — dtype-independent count

    // 0) index dtype detection (1 thread; result consumed later in-stream)
    detect_kernel<<<1, 1>>>((const int*)eidx);

    // 1) self term (initializes out)
    {
        int threads = n_nodes * 4;
        int blk = 256;
        int grid = (threads + blk - 1) / blk;
        self_kernel<<<grid, blk>>>(x, w_self, b_self, out, n_nodes);
    }
    // 2) edge scatter-add
    {
        int threads = n_edges * 4;
        int blk = 256;
        int grid = (threads + blk - 1) / blk;
        edge_kernel<<<grid, blk>>>(x, eidx, w_edge, b_edge, out, n_edges, n_nodes);
    }
    // 3) relu
    {
        int total = n_nodes * D;
        int blk = 256;
        int grid = (total + blk - 1) / blk;
        if (grid > 2048) grid = 2048;
        relu_kernel<<<grid, blk>>>(out, total);
    }
}

// round 4
// speedup vs baseline: 1.0076x; 1.0076x over previous
#include <cuda_runtime.h>
#include <cstdint>

// SheafConvLayer:
//   out[n,:] = relu( W_self[n] @ x[n] + b_self[n]
//                    + sum_{e: dst[e]==n} ( W_edge[e] @ x[src[e]] + b_edge[e] ) )
// D_IN = D_OUT = 16.
//
// Inputs (metadata order):
//   0: x           f32 [N,16]
//   1: edge_index  int [2,E]   (dtype int32 OR int64 — detected at runtime)
//   2: weight_edge f32 [E,16,16]
//   3: weight_self f32 [N,16,16]
//   4: bias_edge   f32 [E,16]
//   5: bias_self   f32 [N,16]
// out: f32 [N,16]

#define D 16

// Runtime-detected flag: 1 if edge_index is int64, 0 if int32.
__device__ int g_idx_is64;

__device__ __forceinline__ float dot4(float4 a, float4 b) {
    return a.x * b.x + a.y * b.y + a.z * b.z + a.w * b.w;
}

// Vector reduction to global memory (sm_90+): one 16B REDG instead of 4 scalar atomics.
__device__ __forceinline__ void red_add_v4(float* addr, float a, float b, float c, float d) {
    asm volatile("red.global.add.v4.f32 [%0], {%1, %2, %3, %4};"
                 :: "l"(addr), "f"(a), "f"(b), "f"(c), "f"(d)
                 : "memory");
}

// ---------------------------------------------------------------------------
// Kernel 0: dtype detection, parallel version. 256 threads each check 4
// odd words (high halves if int64 little-endian) of the first 1024 pairs.
// int64 indices < 2^31 -> all high words zero. int32 data -> random node
// ids there, false-int64 probability ~0. Reads 8KB, fully parallel: ~1-2us
// (the previous single-thread early-exit loop serialized ~40us).
// ---------------------------------------------------------------------------
__global__ void detect_kernel(const int* __restrict__ eidx_words)
{
    int i = threadIdx.x;           // 0..255
    int nz = 0;
    #pragma unroll
    for (int k = 0; k < 4; k++)
        nz |= eidx_words[2 * (i * 4 + k) + 1];
    int any = __syncthreads_or(nz != 0);
    if (i == 0) g_idx_is64 = (any == 0) ? 1 : 0;
}

// ---------------------------------------------------------------------------
// Kernel 1: self term. One thread handles (node, 4-channel group).
// Writes out directly (initializes the poisoned output buffer).
// ---------------------------------------------------------------------------
__global__ void __launch_bounds__(256)
self_kernel(const float* __restrict__ x,
            const float* __restrict__ w_self,
            const float* __restrict__ b_self,
            float* __restrict__ out,
            int n_nodes)
{
    int t = blockIdx.x * blockDim.x + threadIdx.x;
    int total = n_nodes * 4;
    if (t >= total) return;
    int n = t >> 2;
    int q = t & 3;  // channel group: rows q*4 .. q*4+3

    const float4* xp = reinterpret_cast<const float4*>(x + (size_t)n * D);
    float4 x0 = xp[0], x1 = xp[1], x2 = xp[2], x3 = xp[3];

    const float4* wp = reinterpret_cast<const float4*>(w_self + (size_t)n * D * D + (size_t)q * 64);
    float4 bb = reinterpret_cast<const float4*>(b_self + (size_t)n * D)[q];
    float acc[4] = {bb.x, bb.y, bb.z, bb.w};

    #pragma unroll
    for (int r = 0; r < 4; r++) {
        float4 w0 = wp[r * 4 + 0];
        float4 w1 = wp[r * 4 + 1];
        float4 w2 = wp[r * 4 + 2];
        float4 w3 = wp[r * 4 + 3];
        acc[r] += dot4(w0, x0) + dot4(w1, x1) + dot4(w2, x2) + dot4(w3, x3);
    }

    reinterpret_cast<float4*>(out + (size_t)n * D)[q] =
        make_float4(acc[0], acc[1], acc[2], acc[3]);
}

// ---------------------------------------------------------------------------
// Kernel 2: edge messages. One thread handles (edge, 4-channel group).
// Streams a contiguous 256B of weight_edge per thread, gathers x[src]
// (L2-resident), one red.v4.f32 to out[dst]. Index dtype via runtime flag;
// OOB indices skipped (fail loudly via rel_err instead of crashing).
// ---------------------------------------------------------------------------
__global__ void __launch_bounds__(256)
edge_kernel(const float* __restrict__ x,
            const void* __restrict__ edge_index,
            const float* __restrict__ w_edge,
            const float* __restrict__ b_edge,
            float* __restrict__ out,
            int n_edges, int n_nodes)
{
    int t = blockIdx.x * blockDim.x + threadIdx.x;
    int total = n_edges * 4;
    if (t >= total) return;
    int e = t >> 2;
    int q = t & 3;

    long long src, dst;
    if (g_idx_is64) {
        const long long* p = (const long long*)edge_index;
        src = p[e];
        dst = p[(size_t)n_edges + e];
    } else {
        const int* p = (const int*)edge_index;
        src = p[e];
        dst = p[(size_t)n_edges + e];
    }
    // Safety clamp: never dereference garbage.
    if (src < 0 || src >= n_nodes || dst < 0 || dst >= n_nodes) return;

    const float4* xp = reinterpret_cast<const float4*>(x + (size_t)src * D);
    float4 x0 = xp[0], x1 = xp[1], x2 = xp[2], x3 = xp[3];

    const float4* wp = reinterpret_cast<const float4*>(w_edge + (size_t)e * D * D + (size_t)q * 64);
    float4 bb = reinterpret_cast<const float4*>(b_edge + (size_t)e * D)[q];
    float acc[4] = {bb.x, bb.y, bb.z, bb.w};

    #pragma unroll
    for (int r = 0; r < 4; r++) {
        float4 w0 = wp[r * 4 + 0];
        float4 w1 = wp[r * 4 + 1];
        float4 w2 = wp[r * 4 + 2];
        float4 w3 = wp[r * 4 + 3];
        acc[r] += dot4(w0, x0) + dot4(w1, x1) + dot4(w2, x2) + dot4(w3, x3);
    }

    red_add_v4(out + (size_t)dst * D + (size_t)q * 4, acc[0], acc[1], acc[2], acc[3]);
}

// ---------------------------------------------------------------------------
// Kernel 3: ReLU over out, float4-vectorized, exact grid (no grid-stride).
// ---------------------------------------------------------------------------
__global__ void __launch_bounds__(256)
relu_kernel(float4* __restrict__ out, int total4)
{
    int t = blockIdx.x * blockDim.x + threadIdx.x;
    if (t >= total4) return;
    float4 v = out[t];
    v.x = v.x > 0.0f ? v.x : 0.0f;
    v.y = v.y > 0.0f ? v.y : 0.0f;
    v.z = v.z > 0.0f ? v.z : 0.0f;
    v.w = v.w > 0.0f ? v.w : 0.0f;
    out[t] = v;
}

extern "C" void kernel_launch(void* const* d_in, const int* in_sizes, int n_in,
                              void* d_out, int out_size)
{
    const float* x      = (const float*)d_in[0];
    const void*  eidx   = d_in[1];
    const float* w_edge = (const float*)d_in[2];
    const float* w_self = (const float*)d_in[3];
    const float* b_edge = (const float*)d_in[4];
    const float* b_self = (const float*)d_in[5];
    float*       out    = (float*)d_out;

    int n_nodes = in_sizes[0] / D;        // x is [N,16]
    int n_edges = in_sizes[2] / (D * D);  // weight_edge is [E,16,16] — dtype-independent count

    // 0) index dtype detection (1 block, parallel; result consumed in-stream)
    detect_kernel<<<1, 256>>>((const int*)eidx);

    // 1) self term (initializes out)
    {
        int threads = n_nodes * 4;
        int blk = 256;
        int grid = (threads + blk - 1) / blk;
        self_kernel<<<grid, blk>>>(x, w_self, b_self, out, n_nodes);
    }
    // 2) edge scatter-add
    {
        int threads = n_edges * 4;
        int blk = 256;
        int grid = (threads + blk - 1) / blk;
        edge_kernel<<<grid, blk>>>(x, eidx, w_edge, b_edge, out, n_edges, n_nodes);
    }
    // 3) relu (vectorized)
    {
        int total4 = (n_nodes * D) / 4;
        int blk = 256;
        int grid = (total4 + blk - 1) / blk;
        relu_kernel<<<grid, blk>>>((float4*)out, total4);
    }
}